// round 1
// baseline (speedup 1.0000x reference)
#include <cuda_runtime.h>
#include <math.h>

#define BDIM 16
#define SDIM 4096
#define EDIM 512
#define HDIM 8
#define DH   64
#define TOK  (BDIM * SDIM)   // 65536 tokens

// Scratch (allocation-free rule: device globals)
__device__ float g_qkv[(size_t)TOK * 3 * EDIM];  // 402 MB
__device__ float g_o[(size_t)TOK * EDIM];        // 134 MB

// ---------------------------------------------------------------------------
// C[M,N] = A[M,K] * W[N,K]^T + bias[N]   (both operands K-contiguous, "NT")
// BM=BN=128, BK=16, 256 threads, 8x8 per-thread tile.
// All dims here are multiples of tile sizes (M=65536, N in {1536,512}, K=512),
// so no bounds checks.
// ---------------------------------------------------------------------------
__global__ void __launch_bounds__(256) gemm_nt_bias(
    const float* __restrict__ A, const float* __restrict__ W,
    const float* __restrict__ bias, float* __restrict__ C,
    int M, int N, int K)
{
    constexpr int BM = 128, BN = 128, BK = 16, TM = 8, TN = 8;
    __shared__ float As[BK][BM + 4];
    __shared__ float Bs[BK][BN + 4];

    const int tid = threadIdx.x;
    const int bm  = blockIdx.y * BM;
    const int bn  = blockIdx.x * BN;
    const int tx  = tid & 15;   // 0..15 -> N
    const int ty  = tid >> 4;   // 0..15 -> M
    const int lrow  = tid >> 2;         // 0..63
    const int lcol  = (tid & 3) << 2;   // 0,4,8,12

    float acc[TM][TN];
#pragma unroll
    for (int i = 0; i < TM; i++)
#pragma unroll
        for (int j = 0; j < TN; j++) acc[i][j] = 0.0f;

    const float* Aptr = A + (size_t)(bm + lrow) * K + lcol;
    const float* Wptr = W + (size_t)(bn + lrow) * K + lcol;

    for (int k0 = 0; k0 < K; k0 += BK) {
        float4 a0 = *(const float4*)(Aptr + k0);
        float4 a1 = *(const float4*)(Aptr + (size_t)64 * K + k0);
        float4 b0 = *(const float4*)(Wptr + k0);
        float4 b1 = *(const float4*)(Wptr + (size_t)64 * K + k0);

        As[lcol + 0][lrow]      = a0.x;
        As[lcol + 1][lrow]      = a0.y;
        As[lcol + 2][lrow]      = a0.z;
        As[lcol + 3][lrow]      = a0.w;
        As[lcol + 0][lrow + 64] = a1.x;
        As[lcol + 1][lrow + 64] = a1.y;
        As[lcol + 2][lrow + 64] = a1.z;
        As[lcol + 3][lrow + 64] = a1.w;

        Bs[lcol + 0][lrow]      = b0.x;
        Bs[lcol + 1][lrow]      = b0.y;
        Bs[lcol + 2][lrow]      = b0.z;
        Bs[lcol + 3][lrow]      = b0.w;
        Bs[lcol + 0][lrow + 64] = b1.x;
        Bs[lcol + 1][lrow + 64] = b1.y;
        Bs[lcol + 2][lrow + 64] = b1.z;
        Bs[lcol + 3][lrow + 64] = b1.w;

        __syncthreads();

#pragma unroll
        for (int kk = 0; kk < BK; kk++) {
            float4 av0 = *(const float4*)&As[kk][ty * TM];
            float4 av1 = *(const float4*)&As[kk][ty * TM + 4];
            float4 bv0 = *(const float4*)&Bs[kk][tx * TN];
            float4 bv1 = *(const float4*)&Bs[kk][tx * TN + 4];
            float ar[TM] = {av0.x, av0.y, av0.z, av0.w, av1.x, av1.y, av1.z, av1.w};
            float br[TN] = {bv0.x, bv0.y, bv0.z, bv0.w, bv1.x, bv1.y, bv1.z, bv1.w};
#pragma unroll
            for (int i = 0; i < TM; i++)
#pragma unroll
                for (int j = 0; j < TN; j++)
                    acc[i][j] = fmaf(ar[i], br[j], acc[i][j]);
        }
        __syncthreads();
    }

    // Epilogue with bias
#pragma unroll
    for (int i = 0; i < TM; i++) {
        float* crow = C + (size_t)(bm + ty * TM + i) * N + bn + tx * TN;
#pragma unroll
        for (int j = 0; j < TN; j += 4) {
            float4 v;
            v.x = acc[i][j + 0] + bias[bn + tx * TN + j + 0];
            v.y = acc[i][j + 1] + bias[bn + tx * TN + j + 1];
            v.z = acc[i][j + 2] + bias[bn + tx * TN + j + 2];
            v.w = acc[i][j + 3] + bias[bn + tx * TN + j + 3];
            *(float4*)(crow + j) = v;
        }
    }
}

// ---------------------------------------------------------------------------
// Attention: the window reshape in the reference is a no-op; attention runs
// over the batch axis (16) independently at every (s, h).
// One CTA per (s, h). smem stride 66 (not 64) -> max 2-way bank conflicts.
// ---------------------------------------------------------------------------
__global__ void __launch_bounds__(128) attn_kernel(
    const float* __restrict__ qkv, float* __restrict__ o)
{
    const int s = blockIdx.x;   // 0..4095
    const int h = blockIdx.y;   // 0..7

    __shared__ float q[BDIM][66];
    __shared__ float k[BDIM][66];
    __shared__ float v[BDIM][66];
    __shared__ float sc[BDIM][BDIM + 1];

    const int tid = threadIdx.x;   // 128 threads

    // Load q/k/v for all 16 batch rows at this (s, h). Coalesced over d.
    for (int j = tid; j < BDIM * DH; j += 128) {
        const int b = j >> 6;
        const int d = j & 63;
        const size_t base = ((size_t)(b * SDIM + s)) * (3 * EDIM) + h * DH + d;
        q[b][d] = qkv[base];
        k[b][d] = qkv[base + EDIM];
        v[b][d] = qkv[base + 2 * EDIM];
    }
    __syncthreads();

    // Scores: 256 entries, 2 per thread
    const float scale = 0.125f;   // 1/sqrt(64)
#pragma unroll
    for (int e = tid; e < BDIM * BDIM; e += 128) {
        const int bq = e >> 4;
        const int bk = e & 15;
        float acc = 0.0f;
#pragma unroll
        for (int d = 0; d < DH; d++)
            acc = fmaf(q[bq][d], k[bk][d], acc);
        sc[bq][bk] = acc * scale;
    }
    __syncthreads();

    // Softmax over key-batch axis (16 rows, one thread each; tiny)
    if (tid < BDIM) {
        float m = -1e30f;
#pragma unroll
        for (int j = 0; j < BDIM; j++) m = fmaxf(m, sc[tid][j]);
        float sum = 0.0f;
        float e_[BDIM];
#pragma unroll
        for (int j = 0; j < BDIM; j++) { e_[j] = expf(sc[tid][j] - m); sum += e_[j]; }
        const float inv = 1.0f / sum;
#pragma unroll
        for (int j = 0; j < BDIM; j++) sc[tid][j] = e_[j] * inv;
    }
    __syncthreads();

    // O = attn @ V : 1024 outputs, 8 per thread. d layout keeps stores coalesced.
    const int bq = tid >> 3;
    const int dl = tid & 7;
    float* orow = o + ((size_t)(bq * SDIM + s)) * EDIM + h * DH;
#pragma unroll
    for (int i = 0; i < 8; i++) {
        const int d = dl + i * 8;
        float acc = 0.0f;
#pragma unroll
        for (int bk = 0; bk < BDIM; bk++)
            acc = fmaf(sc[bq][bk], v[bk][d], acc);
        orow[d] = acc;
    }
}

// ---------------------------------------------------------------------------
extern "C" void kernel_launch(void* const* d_in, const int* in_sizes, int n_in,
                              void* d_out, int out_size)
{
    const float* x     = (const float*)d_in[0];
    const float* W_in  = (const float*)d_in[1];
    const float* b_in  = (const float*)d_in[2];
    const float* W_out = (const float*)d_in[3];
    const float* b_out = (const float*)d_in[4];
    float* out = (float*)d_out;

    float *qkv, *o;
    cudaGetSymbolAddress((void**)&qkv, g_qkv);
    cudaGetSymbolAddress((void**)&o, g_o);

    // 1) QKV projection: (65536,512) @ (1536,512)^T + b_in
    dim3 g1(3 * EDIM / 128, TOK / 128);
    gemm_nt_bias<<<g1, 256>>>(x, W_in, b_in, qkv, TOK, 3 * EDIM, EDIM);

    // 2) Batch-axis attention at each (s, h)
    dim3 g2(SDIM, HDIM);
    attn_kernel<<<g2, 128>>>(qkv, o);

    // 3) Output projection: (65536,512) @ (512,512)^T + b_out
    dim3 g3(EDIM / 128, TOK / 128);
    gemm_nt_bias<<<g3, 256>>>(o, W_out, b_out, out, TOK, EDIM, EDIM);
}

// round 4
// speedup vs baseline: 1.8995x; 1.8995x over previous
#include <cuda_runtime.h>
#include <cuda_bf16.h>
#include <math.h>
#include <stdint.h>

#define BDIM 16
#define SDIM 4096
#define EDIM 512
#define HDIM 8
#define DH   64
#define TOK  (BDIM * SDIM)   // 65536 tokens
#define KDIM 512

// ---------------------------------------------------------------------------
// Scratch (allocation-free rule: device globals)
// ---------------------------------------------------------------------------
__device__ float          g_qkv[(size_t)TOK * 3 * EDIM];
__device__ __nv_bfloat16  g_xhi[(size_t)TOK * EDIM];
__device__ __nv_bfloat16  g_xlo[(size_t)TOK * EDIM];
__device__ __nv_bfloat16  g_ohi[(size_t)TOK * EDIM];
__device__ __nv_bfloat16  g_olo[(size_t)TOK * EDIM];
__device__ __nv_bfloat16  g_winhi[(size_t)3 * EDIM * EDIM];
__device__ __nv_bfloat16  g_winlo[(size_t)3 * EDIM * EDIM];
__device__ __nv_bfloat16  g_wouthi[(size_t)EDIM * EDIM];
__device__ __nv_bfloat16  g_woutlo[(size_t)EDIM * EDIM];

// ---------------------------------------------------------------------------
// PTX helpers (base PTX only — no sm_103a-gated features)
// ---------------------------------------------------------------------------
__device__ __forceinline__ uint32_t smem_u32(const void* p) {
    uint32_t a;
    asm("{ .reg .u64 t; cvta.to.shared.u64 t, %1; cvt.u32.u64 %0, t; }" : "=r"(a) : "l"(p));
    return a;
}
__device__ __forceinline__ void cpa16(uint32_t dst, const void* src) {
    asm volatile("cp.async.cg.shared.global [%0], [%1], 16;" :: "r"(dst), "l"(src));
}
#define CP_COMMIT() asm volatile("cp.async.commit_group;" ::: "memory")
#define CP_WAIT(n)  asm volatile("cp.async.wait_group %0;" :: "n"(n) : "memory")

__device__ __forceinline__ void ldsm4(uint32_t& r0, uint32_t& r1, uint32_t& r2, uint32_t& r3,
                                      uint32_t addr) {
    asm volatile("ldmatrix.sync.aligned.m8n8.x4.shared.b16 {%0,%1,%2,%3}, [%4];"
                 : "=r"(r0), "=r"(r1), "=r"(r2), "=r"(r3) : "r"(addr));
}
__device__ __forceinline__ void mma16816(float& d0, float& d1, float& d2, float& d3,
                                         uint32_t a0, uint32_t a1, uint32_t a2, uint32_t a3,
                                         uint32_t b0, uint32_t b1) {
    asm volatile(
        "mma.sync.aligned.m16n8k16.row.col.f32.bf16.bf16.f32 "
        "{%0,%1,%2,%3}, {%4,%5,%6,%7}, {%8,%9}, {%0,%1,%2,%3};"
        : "+f"(d0), "+f"(d1), "+f"(d2), "+f"(d3)
        : "r"(a0), "r"(a1), "r"(a2), "r"(a3), "r"(b0), "r"(b1));
}

// Swizzled smem offset within one 128x32-bf16 tile (row=64B, 4 x 16B chunks)
__device__ __forceinline__ uint32_t swz(int row, int ch) {
    return (uint32_t)(row * 64 + ((ch ^ ((row >> 1) & 3)) << 4));
}

// ---------------------------------------------------------------------------
// Elementwise fp32 -> (bf16 hi, bf16 lo) split
// ---------------------------------------------------------------------------
__global__ void __launch_bounds__(256) split_hilo(
    const float4* __restrict__ x, uint2* __restrict__ hi, uint2* __restrict__ lo, int n4)
{
    int i = blockIdx.x * 256 + threadIdx.x;
    if (i >= n4) return;
    float4 v = x[i];
    __nv_bfloat16 h0 = __float2bfloat16(v.x);
    __nv_bfloat16 h1 = __float2bfloat16(v.y);
    __nv_bfloat16 h2 = __float2bfloat16(v.z);
    __nv_bfloat16 h3 = __float2bfloat16(v.w);
    __nv_bfloat16 l0 = __float2bfloat16(v.x - __bfloat162float(h0));
    __nv_bfloat16 l1 = __float2bfloat16(v.y - __bfloat162float(h1));
    __nv_bfloat16 l2 = __float2bfloat16(v.z - __bfloat162float(h2));
    __nv_bfloat16 l3 = __float2bfloat16(v.w - __bfloat162float(h3));
    __nv_bfloat162 hA = {h0, h1}, hB = {h2, h3}, lA = {l0, l1}, lB = {l2, l3};
    uint2 H, L;
    H.x = *(uint32_t*)&hA; H.y = *(uint32_t*)&hB;
    L.x = *(uint32_t*)&lA; L.y = *(uint32_t*)&lB;
    hi[i] = H;
    lo[i] = L;
}

// ---------------------------------------------------------------------------
// HMMA GEMM: C[M,N] = Ahi*Bhi^T + Ahi*Blo^T + Alo*Bhi^T + bias
// 128x128 CTA tile, BK=32, 3-stage cp.async pipeline, 8 warps (64x32 each).
// A, B K-major bf16 (row stride 512). Virtual K loop: 3 passes x 16 chunks.
// ---------------------------------------------------------------------------
#define STAGES 3
#define STAGE_BYTES 16384          // A tile 8KB + B tile 8KB
#define GEMM_SMEM (STAGES * STAGE_BYTES)

__global__ void __launch_bounds__(256) gemm_hmma(
    const __nv_bfloat16* __restrict__ Ahi, const __nv_bfloat16* __restrict__ Alo,
    const __nv_bfloat16* __restrict__ Bhi, const __nv_bfloat16* __restrict__ Blo,
    const float* __restrict__ bias, float* __restrict__ C, int N)
{
    extern __shared__ char smem[];
    const uint32_t sb = smem_u32(smem);
    const int tid = threadIdx.x;
    const int wid = tid >> 5;
    const int lid = tid & 31;
    const int bm = blockIdx.y * 128;
    const int bn = blockIdx.x * 128;

    const int warp_m = (wid >> 2) * 64;   // 0 or 64
    const int warp_n = (wid & 3) * 32;    // 0,32,64,96

    const __nv_bfloat16* passA[3] = { Ahi + (size_t)bm * KDIM,
                                      Ahi + (size_t)bm * KDIM,
                                      Alo + (size_t)bm * KDIM };
    const __nv_bfloat16* passB[3] = { Bhi + (size_t)bn * KDIM,
                                      Blo + (size_t)bn * KDIM,
                                      Bhi + (size_t)bn * KDIM };

    // Per-thread load coords: row = idx>>2, chunk = idx&3 (16B each)
    const int lrow0 = tid >> 2;           // rows 0..63   (i=0)
    const int lch   = tid & 3;

    float acc[4][4][4];                   // [m frag][n frag][4]
#pragma unroll
    for (int i = 0; i < 4; i++)
#pragma unroll
        for (int j = 0; j < 4; j++)
#pragma unroll
            for (int r = 0; r < 4; r++) acc[i][j][r] = 0.0f;

    // ---- async load of one stage for virtual iteration `it`
    auto load_stage = [&](int s, int it) {
        const int pass = it >> 4;
        const int kb = (it & 15) * 32;    // bf16 elem offset in K
        const __nv_bfloat16* sA = passA[pass];
        const __nv_bfloat16* sB = passB[pass];
        const uint32_t abase = sb + s * STAGE_BYTES;
        const uint32_t bbase = abase + 8192;
#pragma unroll
        for (int i = 0; i < 2; i++) {
            const int row = lrow0 + 64 * i;
            cpa16(abase + swz(row, lch), sA + (size_t)row * KDIM + kb + lch * 8);
        }
#pragma unroll
        for (int i = 0; i < 2; i++) {
            const int row = lrow0 + 64 * i;
            cpa16(bbase + swz(row, lch), sB + (size_t)row * KDIM + kb + lch * 8);
        }
        CP_COMMIT();
    };

    // Prolog: stages 0,1
    load_stage(0, 0);
    load_stage(1, 1);

    for (int it = 0; it < 48; it++) {
        CP_WAIT(1);
        __syncthreads();

        const int nxt = it + 2;
        if (nxt < 48) load_stage(nxt % STAGES, nxt);

        const uint32_t abase = sb + (it % STAGES) * STAGE_BYTES;
        const uint32_t bbase = abase + 8192;

#pragma unroll
        for (int ks = 0; ks < 2; ks++) {            // two k16 halves of BK=32
            const int chb = ks * 2;                  // 16B-chunk base for this k16
            uint32_t a[4][4];
            uint32_t b[2][4];
#pragma unroll
            for (int fm = 0; fm < 4; fm++) {
                const int row = warp_m + fm * 16 + (lid & 15);
                ldsm4(a[fm][0], a[fm][1], a[fm][2], a[fm][3],
                      abase + swz(row, chb + (lid >> 4)));
            }
#pragma unroll
            for (int fb = 0; fb < 2; fb++) {
                const int row = warp_n + fb * 16 + (lid & 15);
                ldsm4(b[fb][0], b[fb][1], b[fb][2], b[fb][3],
                      bbase + swz(row, chb + (lid >> 4)));
            }
#pragma unroll
            for (int fm = 0; fm < 4; fm++) {
#pragma unroll
                for (int fn = 0; fn < 4; fn++) {
                    const int fb = fn >> 1;          // which ldsm
                    const int hh = fn & 1;           // n8 half: 0 -> {r0,r2}, 1 -> {r1,r3}
                    mma16816(acc[fm][fn][0], acc[fm][fn][1], acc[fm][fn][2], acc[fm][fn][3],
                             a[fm][0], a[fm][1], a[fm][2], a[fm][3],
                             b[fb][hh], b[fb][hh + 2]);
                }
            }
        }
        __syncthreads();
    }

    // ---- Epilogue: direct fp32 stores + bias
    const int lr = lid >> 2;       // 0..7
    const int lc = (lid & 3) * 2;  // 0,2,4,6
#pragma unroll
    for (int fm = 0; fm < 4; fm++) {
#pragma unroll
        for (int fn = 0; fn < 4; fn++) {
            const int col = bn + warp_n + fn * 8 + lc;
            const float b0 = bias[col], b1 = bias[col + 1];
            const int row0 = bm + warp_m + fm * 16 + lr;
            float2 v0 = { acc[fm][fn][0] + b0, acc[fm][fn][1] + b1 };
            float2 v1 = { acc[fm][fn][2] + b0, acc[fm][fn][3] + b1 };
            *(float2*)(C + (size_t)row0 * N + col)       = v0;
            *(float2*)(C + (size_t)(row0 + 8) * N + col) = v1;
        }
    }
}

// ---------------------------------------------------------------------------
// Attention over the batch axis (16) at each (s, h); emits o split hi/lo bf16.
// ---------------------------------------------------------------------------
__global__ void __launch_bounds__(128) attn_kernel(
    const float* __restrict__ qkv,
    __nv_bfloat16* __restrict__ ohi, __nv_bfloat16* __restrict__ olo)
{
    const int s = blockIdx.x;
    const int h = blockIdx.y;

    __shared__ float q[BDIM][66];
    __shared__ float k[BDIM][66];
    __shared__ float v[BDIM][66];
    __shared__ float sc[BDIM][BDIM + 1];

    const int tid = threadIdx.x;

    for (int j = tid; j < BDIM * DH; j += 128) {
        const int b = j >> 6;
        const int d = j & 63;
        const size_t base = ((size_t)(b * SDIM + s)) * (3 * EDIM) + h * DH + d;
        q[b][d] = qkv[base];
        k[b][d] = qkv[base + EDIM];
        v[b][d] = qkv[base + 2 * EDIM];
    }
    __syncthreads();

    const float scale = 0.125f;
#pragma unroll
    for (int e = tid; e < BDIM * BDIM; e += 128) {
        const int bq = e >> 4;
        const int bk = e & 15;
        float acc = 0.0f;
#pragma unroll
        for (int d = 0; d < DH; d++)
            acc = fmaf(q[bq][d], k[bk][d], acc);
        sc[bq][bk] = acc * scale;
    }
    __syncthreads();

    if (tid < BDIM) {
        float m = -1e30f;
#pragma unroll
        for (int j = 0; j < BDIM; j++) m = fmaxf(m, sc[tid][j]);
        float sum = 0.0f;
        float e_[BDIM];
#pragma unroll
        for (int j = 0; j < BDIM; j++) { e_[j] = expf(sc[tid][j] - m); sum += e_[j]; }
        const float inv = 1.0f / sum;
#pragma unroll
        for (int j = 0; j < BDIM; j++) sc[tid][j] = e_[j] * inv;
    }
    __syncthreads();

    const int bq = tid >> 3;
    const int dl = tid & 7;
    const size_t obase = ((size_t)(bq * SDIM + s)) * EDIM + h * DH;
#pragma unroll
    for (int i = 0; i < 8; i++) {
        const int d = dl + i * 8;
        float acc = 0.0f;
#pragma unroll
        for (int bk = 0; bk < BDIM; bk++)
            acc = fmaf(sc[bq][bk], v[bk][d], acc);
        __nv_bfloat16 hi = __float2bfloat16(acc);
        ohi[obase + d] = hi;
        olo[obase + d] = __float2bfloat16(acc - __bfloat162float(hi));
    }
}

// ---------------------------------------------------------------------------
extern "C" void kernel_launch(void* const* d_in, const int* in_sizes, int n_in,
                              void* d_out, int out_size)
{
    const float* x     = (const float*)d_in[0];
    const float* W_in  = (const float*)d_in[1];
    const float* b_in  = (const float*)d_in[2];
    const float* W_out = (const float*)d_in[3];
    const float* b_out = (const float*)d_in[4];
    float* out = (float*)d_out;

    float *qkv;
    __nv_bfloat16 *xhi, *xlo, *ohi, *olo, *winhi, *winlo, *wouthi, *woutlo;
    cudaGetSymbolAddress((void**)&qkv, g_qkv);
    cudaGetSymbolAddress((void**)&xhi, g_xhi);
    cudaGetSymbolAddress((void**)&xlo, g_xlo);
    cudaGetSymbolAddress((void**)&ohi, g_ohi);
    cudaGetSymbolAddress((void**)&olo, g_olo);
    cudaGetSymbolAddress((void**)&winhi, g_winhi);
    cudaGetSymbolAddress((void**)&winlo, g_winlo);
    cudaGetSymbolAddress((void**)&wouthi, g_wouthi);
    cudaGetSymbolAddress((void**)&woutlo, g_woutlo);

    cudaFuncSetAttribute(gemm_hmma, cudaFuncAttributeMaxDynamicSharedMemorySize, GEMM_SMEM);

    // fp32 -> bf16 hi/lo splits
    {
        int n4 = TOK * EDIM / 4;
        split_hilo<<<(n4 + 255) / 256, 256>>>((const float4*)x, (uint2*)xhi, (uint2*)xlo, n4);
        n4 = 3 * EDIM * EDIM / 4;
        split_hilo<<<(n4 + 255) / 256, 256>>>((const float4*)W_in, (uint2*)winhi, (uint2*)winlo, n4);
        n4 = EDIM * EDIM / 4;
        split_hilo<<<(n4 + 255) / 256, 256>>>((const float4*)W_out, (uint2*)wouthi, (uint2*)woutlo, n4);
    }

    // 1) QKV projection -> fp32 qkv
    dim3 g1(3 * EDIM / 128, TOK / 128);
    gemm_hmma<<<g1, 256, GEMM_SMEM>>>(xhi, xlo, winhi, winlo, b_in, qkv, 3 * EDIM);

    // 2) Batch-axis attention; emits o split hi/lo bf16
    dim3 g2(SDIM, HDIM);
    attn_kernel<<<g2, 128>>>(qkv, ohi, olo);

    // 3) Output projection
    dim3 g3(EDIM / 128, TOK / 128);
    gemm_hmma<<<g3, 256, GEMM_SMEM>>>(ohi, olo, wouthi, woutlo, b_out, out, EDIM);
}

// round 5
// speedup vs baseline: 2.1210x; 1.1166x over previous
#include <cuda_runtime.h>
#include <cuda_bf16.h>
#include <math.h>
#include <stdint.h>

#define BDIM 16
#define SDIM 4096
#define EDIM 512
#define HDIM 8
#define DH   64
#define TOK  (BDIM * SDIM)   // 65536 tokens
#define KDIM 512

// ---------------------------------------------------------------------------
// Scratch (allocation-free rule: device globals)
// ---------------------------------------------------------------------------
__device__ float          g_qkv[(size_t)TOK * 3 * EDIM];
__device__ __nv_bfloat16  g_xhi[(size_t)TOK * EDIM];
__device__ __nv_bfloat16  g_xlo[(size_t)TOK * EDIM];
__device__ __nv_bfloat16  g_ohi[(size_t)TOK * EDIM];
__device__ __nv_bfloat16  g_olo[(size_t)TOK * EDIM];
__device__ __nv_bfloat16  g_winhi[(size_t)3 * EDIM * EDIM];
__device__ __nv_bfloat16  g_winlo[(size_t)3 * EDIM * EDIM];
__device__ __nv_bfloat16  g_wouthi[(size_t)EDIM * EDIM];
__device__ __nv_bfloat16  g_woutlo[(size_t)EDIM * EDIM];

// ---------------------------------------------------------------------------
// PTX helpers (base PTX only — no sm_103a-gated features)
// ---------------------------------------------------------------------------
__device__ __forceinline__ uint32_t smem_u32(const void* p) {
    uint32_t a;
    asm("{ .reg .u64 t; cvta.to.shared.u64 t, %1; cvt.u32.u64 %0, t; }" : "=r"(a) : "l"(p));
    return a;
}
__device__ __forceinline__ void cpa16(uint32_t dst, const void* src) {
    asm volatile("cp.async.cg.shared.global [%0], [%1], 16;" :: "r"(dst), "l"(src));
}
#define CP_COMMIT() asm volatile("cp.async.commit_group;" ::: "memory")
#define CP_WAIT(n)  asm volatile("cp.async.wait_group %0;" :: "n"(n) : "memory")

__device__ __forceinline__ void ldsm4(uint32_t& r0, uint32_t& r1, uint32_t& r2, uint32_t& r3,
                                      uint32_t addr) {
    asm volatile("ldmatrix.sync.aligned.m8n8.x4.shared.b16 {%0,%1,%2,%3}, [%4];"
                 : "=r"(r0), "=r"(r1), "=r"(r2), "=r"(r3) : "r"(addr));
}
__device__ __forceinline__ void mma16816(float& d0, float& d1, float& d2, float& d3,
                                         uint32_t a0, uint32_t a1, uint32_t a2, uint32_t a3,
                                         uint32_t b0, uint32_t b1) {
    asm volatile(
        "mma.sync.aligned.m16n8k16.row.col.f32.bf16.bf16.f32 "
        "{%0,%1,%2,%3}, {%4,%5,%6,%7}, {%8,%9}, {%0,%1,%2,%3};"
        : "+f"(d0), "+f"(d1), "+f"(d2), "+f"(d3)
        : "r"(a0), "r"(a1), "r"(a2), "r"(a3), "r"(b0), "r"(b1));
}

// Swizzled smem offset within one 128x32-bf16 tile (row=64B, 4 x 16B chunks)
__device__ __forceinline__ uint32_t swz(int row, int ch) {
    return (uint32_t)(row * 64 + ((ch ^ ((row >> 1) & 3)) << 4));
}

// ---------------------------------------------------------------------------
// Elementwise fp32 -> (bf16 hi, bf16 lo) split
// ---------------------------------------------------------------------------
__global__ void __launch_bounds__(256) split_hilo(
    const float4* __restrict__ x, uint2* __restrict__ hi, uint2* __restrict__ lo, int n4)
{
    int i = blockIdx.x * 256 + threadIdx.x;
    if (i >= n4) return;
    float4 v = x[i];
    __nv_bfloat16 h0 = __float2bfloat16(v.x);
    __nv_bfloat16 h1 = __float2bfloat16(v.y);
    __nv_bfloat16 h2 = __float2bfloat16(v.z);
    __nv_bfloat16 h3 = __float2bfloat16(v.w);
    __nv_bfloat16 l0 = __float2bfloat16(v.x - __bfloat162float(h0));
    __nv_bfloat16 l1 = __float2bfloat16(v.y - __bfloat162float(h1));
    __nv_bfloat16 l2 = __float2bfloat16(v.z - __bfloat162float(h2));
    __nv_bfloat16 l3 = __float2bfloat16(v.w - __bfloat162float(h3));
    __nv_bfloat162 hA = {h0, h1}, hB = {h2, h3}, lA = {l0, l1}, lB = {l2, l3};
    uint2 H, L;
    H.x = *(uint32_t*)&hA; H.y = *(uint32_t*)&hB;
    L.x = *(uint32_t*)&lA; L.y = *(uint32_t*)&lB;
    hi[i] = H;
    lo[i] = L;
}

// ---------------------------------------------------------------------------
// HMMA GEMM: C = Ahi*Bhi^T + Ahi*Blo^T + Alo*Bhi^T + bias
// 128x128 CTA tile, BK=32. Per K-chunk all 4 tiles (Ahi,Alo,Bhi,Blo) are
// loaded once and 3 passes accumulate from them: 16 iterations total,
// 1 __syncthreads per iteration, 3 rotating 32KB stages (distance-2 prefetch).
// ---------------------------------------------------------------------------
#define STAGES 3
#define TILE8K 8192
#define STAGE_BYTES (4 * TILE8K)   // Ahi | Alo | Bhi | Blo
#define GEMM_SMEM (STAGES * STAGE_BYTES)
#define NCHUNK 16

__global__ void __launch_bounds__(256) gemm_hmma(
    const __nv_bfloat16* __restrict__ Ahi, const __nv_bfloat16* __restrict__ Alo,
    const __nv_bfloat16* __restrict__ Bhi, const __nv_bfloat16* __restrict__ Blo,
    const float* __restrict__ bias, float* __restrict__ C, int N)
{
    extern __shared__ char smem[];
    const uint32_t sb = smem_u32(smem);
    const int tid = threadIdx.x;
    const int wid = tid >> 5;
    const int lid = tid & 31;
    const int bm = blockIdx.y * 128;
    const int bn = blockIdx.x * 128;

    const int warp_m = (wid >> 2) * 64;   // 0 or 64
    const int warp_n = (wid & 3) * 32;    // 0,32,64,96

    const __nv_bfloat16* srcs[4] = {
        Ahi + (size_t)bm * KDIM, Alo + (size_t)bm * KDIM,
        Bhi + (size_t)bn * KDIM, Blo + (size_t)bn * KDIM };

    const int lrow0 = tid >> 2;           // 0..63
    const int lch   = tid & 3;

    float acc[4][4][4];
#pragma unroll
    for (int i = 0; i < 4; i++)
#pragma unroll
        for (int j = 0; j < 4; j++)
#pragma unroll
            for (int r = 0; r < 4; r++) acc[i][j][r] = 0.0f;

    // Precomputed ldsm offsets (ks=0; ks=1 differs by ^32)
    uint32_t offA[4], offB[2];
#pragma unroll
    for (int fm = 0; fm < 4; fm++)
        offA[fm] = swz(warp_m + fm * 16 + (lid & 15), lid >> 4);
#pragma unroll
    for (int fb = 0; fb < 2; fb++)
        offB[fb] = swz(warp_n + fb * 16 + (lid & 15), lid >> 4);

    auto load_stage = [&](uint32_t sbase, int kc) {
        const int kb = kc * 32;
#pragma unroll
        for (int t = 0; t < 4; t++) {
            const __nv_bfloat16* src = srcs[t];
            const uint32_t tb = sbase + t * TILE8K;
            cpa16(tb + swz(lrow0, lch),
                  src + (size_t)lrow0 * KDIM + kb + lch * 8);
            cpa16(tb + swz(lrow0 + 64, lch),
                  src + (size_t)(lrow0 + 64) * KDIM + kb + lch * 8);
        }
        CP_COMMIT();
    };

    uint32_t sCur = sb, sNxt = sb + STAGE_BYTES, sPrv = sb + 2 * STAGE_BYTES;

    load_stage(sCur, 0);
    load_stage(sNxt, 1);

    for (int it = 0; it < NCHUNK; it++) {
        if (it < NCHUNK - 1) { CP_WAIT(1); } else { CP_WAIT(0); }
        __syncthreads();

        if (it + 2 < NCHUNK) load_stage(sPrv, it + 2);

#pragma unroll
        for (int ks = 0; ks < 2; ks++) {
            const uint32_t kx = ks << 5;          // ^32 for second k16
            uint32_t a[4][4], bh[2][4], bl[2][4];
#pragma unroll
            for (int fm = 0; fm < 4; fm++)
                ldsm4(a[fm][0], a[fm][1], a[fm][2], a[fm][3],
                      sCur + (offA[fm] ^ kx));                       // Ahi
#pragma unroll
            for (int fb = 0; fb < 2; fb++)
                ldsm4(bh[fb][0], bh[fb][1], bh[fb][2], bh[fb][3],
                      sCur + 2 * TILE8K + (offB[fb] ^ kx));          // Bhi
#pragma unroll
            for (int fb = 0; fb < 2; fb++)
                ldsm4(bl[fb][0], bl[fb][1], bl[fb][2], bl[fb][3],
                      sCur + 3 * TILE8K + (offB[fb] ^ kx));          // Blo

#pragma unroll
            for (int fm = 0; fm < 4; fm++)
#pragma unroll
                for (int fn = 0; fn < 4; fn++) {
                    const int fb = fn >> 1, hh = fn & 1;
                    mma16816(acc[fm][fn][0], acc[fm][fn][1], acc[fm][fn][2], acc[fm][fn][3],
                             a[fm][0], a[fm][1], a[fm][2], a[fm][3],
                             bh[fb][hh], bh[fb][hh + 2]);            // Ahi*Bhi
                }
#pragma unroll
            for (int fm = 0; fm < 4; fm++)
#pragma unroll
                for (int fn = 0; fn < 4; fn++) {
                    const int fb = fn >> 1, hh = fn & 1;
                    mma16816(acc[fm][fn][0], acc[fm][fn][1], acc[fm][fn][2], acc[fm][fn][3],
                             a[fm][0], a[fm][1], a[fm][2], a[fm][3],
                             bl[fb][hh], bl[fb][hh + 2]);            // Ahi*Blo
                }
#pragma unroll
            for (int fm = 0; fm < 4; fm++)
                ldsm4(a[fm][0], a[fm][1], a[fm][2], a[fm][3],
                      sCur + TILE8K + (offA[fm] ^ kx));              // Alo (reuse regs)
#pragma unroll
            for (int fm = 0; fm < 4; fm++)
#pragma unroll
                for (int fn = 0; fn < 4; fn++) {
                    const int fb = fn >> 1, hh = fn & 1;
                    mma16816(acc[fm][fn][0], acc[fm][fn][1], acc[fm][fn][2], acc[fm][fn][3],
                             a[fm][0], a[fm][1], a[fm][2], a[fm][3],
                             bh[fb][hh], bh[fb][hh + 2]);            // Alo*Bhi
                }
        }

        // rotate stages: prefetch target cycles through consumed slots
        const uint32_t t = sPrv;
        sPrv = sCur; sCur = sNxt; sNxt = t;
    }

    // ---- Epilogue: direct fp32 stores + bias
    const int lr = lid >> 2;
    const int lc = (lid & 3) * 2;
#pragma unroll
    for (int fm = 0; fm < 4; fm++) {
#pragma unroll
        for (int fn = 0; fn < 4; fn++) {
            const int col = bn + warp_n + fn * 8 + lc;
            const float b0 = bias[col], b1 = bias[col + 1];
            const int row0 = bm + warp_m + fm * 16 + lr;
            float2 v0 = { acc[fm][fn][0] + b0, acc[fm][fn][1] + b1 };
            float2 v1 = { acc[fm][fn][2] + b0, acc[fm][fn][3] + b1 };
            *(float2*)(C + (size_t)row0 * N + col)       = v0;
            *(float2*)(C + (size_t)(row0 + 8) * N + col) = v1;
        }
    }
}

// ---------------------------------------------------------------------------
// Attention over the batch axis (16) at each (s, h); emits o split hi/lo bf16.
// ---------------------------------------------------------------------------
__global__ void __launch_bounds__(128) attn_kernel(
    const float* __restrict__ qkv,
    __nv_bfloat16* __restrict__ ohi, __nv_bfloat16* __restrict__ olo)
{
    const int s = blockIdx.x;
    const int h = blockIdx.y;

    __shared__ float q[BDIM][66];
    __shared__ float k[BDIM][66];
    __shared__ float v[BDIM][66];
    __shared__ float sc[BDIM][BDIM + 1];

    const int tid = threadIdx.x;

    for (int j = tid; j < BDIM * DH; j += 128) {
        const int b = j >> 6;
        const int d = j & 63;
        const size_t base = ((size_t)(b * SDIM + s)) * (3 * EDIM) + h * DH + d;
        q[b][d] = qkv[base];
        k[b][d] = qkv[base + EDIM];
        v[b][d] = qkv[base + 2 * EDIM];
    }
    __syncthreads();

    const float scale = 0.125f;
#pragma unroll
    for (int e = tid; e < BDIM * BDIM; e += 128) {
        const int bq = e >> 4;
        const int bk = e & 15;
        float acc = 0.0f;
#pragma unroll
        for (int d = 0; d < DH; d++)
            acc = fmaf(q[bq][d], k[bk][d], acc);
        sc[bq][bk] = acc * scale;
    }
    __syncthreads();

    if (tid < BDIM) {
        float m = -1e30f;
#pragma unroll
        for (int j = 0; j < BDIM; j++) m = fmaxf(m, sc[tid][j]);
        float sum = 0.0f;
        float e_[BDIM];
#pragma unroll
        for (int j = 0; j < BDIM; j++) { e_[j] = expf(sc[tid][j] - m); sum += e_[j]; }
        const float inv = 1.0f / sum;
#pragma unroll
        for (int j = 0; j < BDIM; j++) sc[tid][j] = e_[j] * inv;
    }
    __syncthreads();

    const int bq = tid >> 3;
    const int dl = tid & 7;
    const size_t obase = ((size_t)(bq * SDIM + s)) * EDIM + h * DH;
#pragma unroll
    for (int i = 0; i < 8; i++) {
        const int d = dl + i * 8;
        float acc = 0.0f;
#pragma unroll
        for (int bk = 0; bk < BDIM; bk++)
            acc = fmaf(sc[bq][bk], v[bk][d], acc);
        __nv_bfloat16 hi = __float2bfloat16(acc);
        ohi[obase + d] = hi;
        olo[obase + d] = __float2bfloat16(acc - __bfloat162float(hi));
    }
}

// ---------------------------------------------------------------------------
extern "C" void kernel_launch(void* const* d_in, const int* in_sizes, int n_in,
                              void* d_out, int out_size)
{
    const float* x     = (const float*)d_in[0];
    const float* W_in  = (const float*)d_in[1];
    const float* b_in  = (const float*)d_in[2];
    const float* W_out = (const float*)d_in[3];
    const float* b_out = (const float*)d_in[4];
    float* out = (float*)d_out;

    float *qkv;
    __nv_bfloat16 *xhi, *xlo, *ohi, *olo, *winhi, *winlo, *wouthi, *woutlo;
    cudaGetSymbolAddress((void**)&qkv, g_qkv);
    cudaGetSymbolAddress((void**)&xhi, g_xhi);
    cudaGetSymbolAddress((void**)&xlo, g_xlo);
    cudaGetSymbolAddress((void**)&ohi, g_ohi);
    cudaGetSymbolAddress((void**)&olo, g_olo);
    cudaGetSymbolAddress((void**)&winhi, g_winhi);
    cudaGetSymbolAddress((void**)&winlo, g_winlo);
    cudaGetSymbolAddress((void**)&wouthi, g_wouthi);
    cudaGetSymbolAddress((void**)&woutlo, g_woutlo);

    cudaFuncSetAttribute(gemm_hmma, cudaFuncAttributeMaxDynamicSharedMemorySize, GEMM_SMEM);

    // fp32 -> bf16 hi/lo splits
    {
        int n4 = TOK * EDIM / 4;
        split_hilo<<<(n4 + 255) / 256, 256>>>((const float4*)x, (uint2*)xhi, (uint2*)xlo, n4);
        n4 = 3 * EDIM * EDIM / 4;
        split_hilo<<<(n4 + 255) / 256, 256>>>((const float4*)W_in, (uint2*)winhi, (uint2*)winlo, n4);
        n4 = EDIM * EDIM / 4;
        split_hilo<<<(n4 + 255) / 256, 256>>>((const float4*)W_out, (uint2*)wouthi, (uint2*)woutlo, n4);
    }

    // 1) QKV projection -> fp32 qkv
    dim3 g1(3 * EDIM / 128, TOK / 128);
    gemm_hmma<<<g1, 256, GEMM_SMEM>>>(xhi, xlo, winhi, winlo, b_in, qkv, 3 * EDIM);

    // 2) Batch-axis attention; emits o split hi/lo bf16
    dim3 g2(SDIM, HDIM);
    attn_kernel<<<g2, 128>>>(qkv, ohi, olo);

    // 3) Output projection
    dim3 g3(EDIM / 128, TOK / 128);
    gemm_hmma<<<g3, 256, GEMM_SMEM>>>(ohi, olo, wouthi, woutlo, b_out, out, EDIM);
}

// round 6
// speedup vs baseline: 2.1902x; 1.0326x over previous
#include <cuda_runtime.h>
#include <cuda_bf16.h>
#include <math.h>
#include <stdint.h>

#define BDIM 16
#define SDIM 4096
#define EDIM 512
#define HDIM 8
#define DH   64
#define TOK  (BDIM * SDIM)   // 65536 tokens
#define KDIM 512

// ---------------------------------------------------------------------------
// Scratch (allocation-free rule: device globals)
// ---------------------------------------------------------------------------
__device__ float          g_qkv[(size_t)TOK * 3 * EDIM];
__device__ __nv_bfloat16  g_xhi[(size_t)TOK * EDIM];
__device__ __nv_bfloat16  g_xlo[(size_t)TOK * EDIM];
__device__ __nv_bfloat16  g_ohi[(size_t)TOK * EDIM];
__device__ __nv_bfloat16  g_olo[(size_t)TOK * EDIM];
__device__ __nv_bfloat16  g_winhi[(size_t)3 * EDIM * EDIM];
__device__ __nv_bfloat16  g_winlo[(size_t)3 * EDIM * EDIM];
__device__ __nv_bfloat16  g_wouthi[(size_t)EDIM * EDIM];
__device__ __nv_bfloat16  g_woutlo[(size_t)EDIM * EDIM];

// ---------------------------------------------------------------------------
// PTX helpers (base PTX only — no sm_103a-gated features)
// ---------------------------------------------------------------------------
__device__ __forceinline__ uint32_t smem_u32(const void* p) {
    uint32_t a;
    asm("{ .reg .u64 t; cvta.to.shared.u64 t, %1; cvt.u32.u64 %0, t; }" : "=r"(a) : "l"(p));
    return a;
}
__device__ __forceinline__ void cpa16(uint32_t dst, const void* src) {
    asm volatile("cp.async.cg.shared.global [%0], [%1], 16;" :: "r"(dst), "l"(src));
}
#define CP_COMMIT() asm volatile("cp.async.commit_group;" ::: "memory")
#define CP_WAIT(n)  asm volatile("cp.async.wait_group %0;" :: "n"(n) : "memory")

__device__ __forceinline__ void ldsm4(uint32_t& r0, uint32_t& r1, uint32_t& r2, uint32_t& r3,
                                      uint32_t addr) {
    asm volatile("ldmatrix.sync.aligned.m8n8.x4.shared.b16 {%0,%1,%2,%3}, [%4];"
                 : "=r"(r0), "=r"(r1), "=r"(r2), "=r"(r3) : "r"(addr));
}
__device__ __forceinline__ void mma16816(float& d0, float& d1, float& d2, float& d3,
                                         uint32_t a0, uint32_t a1, uint32_t a2, uint32_t a3,
                                         uint32_t b0, uint32_t b1) {
    asm volatile(
        "mma.sync.aligned.m16n8k16.row.col.f32.bf16.bf16.f32 "
        "{%0,%1,%2,%3}, {%4,%5,%6,%7}, {%8,%9}, {%0,%1,%2,%3};"
        : "+f"(d0), "+f"(d1), "+f"(d2), "+f"(d3)
        : "r"(a0), "r"(a1), "r"(a2), "r"(a3), "r"(b0), "r"(b1));
}

// Swizzled smem offset within one 128x32-bf16 tile (row=64B, 4 x 16B chunks)
__device__ __forceinline__ uint32_t swz(int row, int ch) {
    return (uint32_t)(row * 64 + ((ch ^ ((row >> 1) & 3)) << 4));
}

// ---------------------------------------------------------------------------
// Elementwise fp32 -> (bf16 hi, bf16 lo) split
// ---------------------------------------------------------------------------
__global__ void __launch_bounds__(256) split_hilo(
    const float4* __restrict__ x, uint2* __restrict__ hi, uint2* __restrict__ lo, int n4)
{
    int i = blockIdx.x * 256 + threadIdx.x;
    if (i >= n4) return;
    float4 v = x[i];
    __nv_bfloat16 h0 = __float2bfloat16(v.x);
    __nv_bfloat16 h1 = __float2bfloat16(v.y);
    __nv_bfloat16 h2 = __float2bfloat16(v.z);
    __nv_bfloat16 h3 = __float2bfloat16(v.w);
    __nv_bfloat16 l0 = __float2bfloat16(v.x - __bfloat162float(h0));
    __nv_bfloat16 l1 = __float2bfloat16(v.y - __bfloat162float(h1));
    __nv_bfloat16 l2 = __float2bfloat16(v.z - __bfloat162float(h2));
    __nv_bfloat16 l3 = __float2bfloat16(v.w - __bfloat162float(h3));
    __nv_bfloat162 hA = {h0, h1}, hB = {h2, h3}, lA = {l0, l1}, lB = {l2, l3};
    uint2 H, L;
    H.x = *(uint32_t*)&hA; H.y = *(uint32_t*)&hB;
    L.x = *(uint32_t*)&lA; L.y = *(uint32_t*)&lB;
    hi[i] = H;
    lo[i] = L;
}

// ---------------------------------------------------------------------------
// HMMA GEMM: C = Ahi*Bhi^T + Ahi*Blo^T + Alo*Bhi^T + bias
// 128x128 CTA tile, BK=32, 16 iterations, 3 rotating 32KB stages.
// Per k16: 10 ldsm upfront (Ahi, Alo, Bhi) -> 32 MMAs -> 2 ldsm (Blo over
// Alo regs) -> 16 MMAs. All addresses hoisted out of the loop.
// ---------------------------------------------------------------------------
#define STAGES 3
#define TILE8K 8192
#define STAGE_BYTES (4 * TILE8K)   // Ahi | Alo | Bhi | Blo
#define GEMM_SMEM (STAGES * STAGE_BYTES)
#define NCHUNK 16

__global__ void __launch_bounds__(256, 2) gemm_hmma(
    const __nv_bfloat16* __restrict__ Ahi, const __nv_bfloat16* __restrict__ Alo,
    const __nv_bfloat16* __restrict__ Bhi, const __nv_bfloat16* __restrict__ Blo,
    const float* __restrict__ bias, float* __restrict__ C, int N)
{
    extern __shared__ char smem[];
    const uint32_t sb = smem_u32(smem);
    const int tid = threadIdx.x;
    const int wid = tid >> 5;
    const int lid = tid & 31;
    const int bm = blockIdx.y * 128;
    const int bn = blockIdx.x * 128;

    const int warp_m = (wid >> 2) * 64;   // 0 or 64
    const int warp_n = (wid & 3) * 32;    // 0,32,64,96

    // ---- hoisted load addressing: 4 advancing src pointers + 2 dst offsets
    const int lrow0 = tid >> 2;           // 0..63
    const int lch   = tid & 3;
    const uint32_t dOff0 = swz(lrow0, lch);
    const uint32_t dOff1 = swz(lrow0 + 64, lch);
    const size_t rowd = (size_t)lrow0 * KDIM + lch * 8;

    const __nv_bfloat16* pT[4] = {
        Ahi + (size_t)bm * KDIM + rowd, Alo + (size_t)bm * KDIM + rowd,
        Bhi + (size_t)bn * KDIM + rowd, Blo + (size_t)bn * KDIM + rowd };

    float acc[4][4][4];
#pragma unroll
    for (int i = 0; i < 4; i++)
#pragma unroll
        for (int j = 0; j < 4; j++)
#pragma unroll
            for (int r = 0; r < 4; r++) acc[i][j][r] = 0.0f;

    // Precomputed ldsm offsets (ks=0; ks=1 differs by ^32)
    uint32_t offA[4], offB[2];
#pragma unroll
    for (int fm = 0; fm < 4; fm++)
        offA[fm] = swz(warp_m + fm * 16 + (lid & 15), lid >> 4);
#pragma unroll
    for (int fb = 0; fb < 2; fb++)
        offB[fb] = swz(warp_n + fb * 16 + (lid & 15), lid >> 4);

    auto load_stage = [&](uint32_t sbase) {
#pragma unroll
        for (int t = 0; t < 4; t++) {
            const uint32_t tb = sbase + t * TILE8K;
            cpa16(tb + dOff0, pT[t]);
            cpa16(tb + dOff1, pT[t] + (size_t)64 * KDIM);
            pT[t] += 32;
        }
        CP_COMMIT();
    };

    uint32_t sCur = sb, sNxt = sb + STAGE_BYTES, sPrv = sb + 2 * STAGE_BYTES;

    load_stage(sCur);
    load_stage(sNxt);

    for (int it = 0; it < NCHUNK; it++) {
        if (it < NCHUNK - 1) { CP_WAIT(1); } else { CP_WAIT(0); }
        __syncthreads();

        if (it + 2 < NCHUNK) load_stage(sPrv);

#pragma unroll
        for (int ks = 0; ks < 2; ks++) {
            const uint32_t kx = ks << 5;
            uint32_t a[4][4], al[4][4], bh[2][4];
            // 10 ldsm upfront: Ahi, Alo, Bhi
#pragma unroll
            for (int fm = 0; fm < 4; fm++)
                ldsm4(a[fm][0], a[fm][1], a[fm][2], a[fm][3],
                      sCur + (offA[fm] ^ kx));
#pragma unroll
            for (int fm = 0; fm < 4; fm++)
                ldsm4(al[fm][0], al[fm][1], al[fm][2], al[fm][3],
                      sCur + TILE8K + (offA[fm] ^ kx));
#pragma unroll
            for (int fb = 0; fb < 2; fb++)
                ldsm4(bh[fb][0], bh[fb][1], bh[fb][2], bh[fb][3],
                      sCur + 2 * TILE8K + (offB[fb] ^ kx));

            // 32 MMAs: Ahi*Bhi then Alo*Bhi
#pragma unroll
            for (int fm = 0; fm < 4; fm++)
#pragma unroll
                for (int fn = 0; fn < 4; fn++) {
                    const int fb = fn >> 1, hh = fn & 1;
                    mma16816(acc[fm][fn][0], acc[fm][fn][1], acc[fm][fn][2], acc[fm][fn][3],
                             a[fm][0], a[fm][1], a[fm][2], a[fm][3],
                             bh[fb][hh], bh[fb][hh + 2]);
                }
#pragma unroll
            for (int fm = 0; fm < 4; fm++)
#pragma unroll
                for (int fn = 0; fn < 4; fn++) {
                    const int fb = fn >> 1, hh = fn & 1;
                    mma16816(acc[fm][fn][0], acc[fm][fn][1], acc[fm][fn][2], acc[fm][fn][3],
                             al[fm][0], al[fm][1], al[fm][2], al[fm][3],
                             bh[fb][hh], bh[fb][hh + 2]);
                }

            // Blo reuses Alo's first two fragment groups (WAR only)
#pragma unroll
            for (int fb = 0; fb < 2; fb++)
                ldsm4(al[fb][0], al[fb][1], al[fb][2], al[fb][3],
                      sCur + 3 * TILE8K + (offB[fb] ^ kx));

            // 16 MMAs: Ahi*Blo
#pragma unroll
            for (int fm = 0; fm < 4; fm++)
#pragma unroll
                for (int fn = 0; fn < 4; fn++) {
                    const int fb = fn >> 1, hh = fn & 1;
                    mma16816(acc[fm][fn][0], acc[fm][fn][1], acc[fm][fn][2], acc[fm][fn][3],
                             a[fm][0], a[fm][1], a[fm][2], a[fm][3],
                             al[fb][hh], al[fb][hh + 2]);
                }
        }

        const uint32_t t = sPrv;
        sPrv = sCur; sCur = sNxt; sNxt = t;
    }

    // ---- Epilogue: direct fp32 stores + bias
    const int lr = lid >> 2;
    const int lc = (lid & 3) * 2;
#pragma unroll
    for (int fm = 0; fm < 4; fm++) {
#pragma unroll
        for (int fn = 0; fn < 4; fn++) {
            const int col = bn + warp_n + fn * 8 + lc;
            const float b0 = bias[col], b1 = bias[col + 1];
            const int row0 = bm + warp_m + fm * 16 + lr;
            float2 v0 = { acc[fm][fn][0] + b0, acc[fm][fn][1] + b1 };
            float2 v1 = { acc[fm][fn][2] + b0, acc[fm][fn][3] + b1 };
            *(float2*)(C + (size_t)row0 * N + col)       = v0;
            *(float2*)(C + (size_t)(row0 + 8) * N + col) = v1;
        }
    }
}

// ---------------------------------------------------------------------------
// Attention over the batch axis (16) at each (s, h); emits o split hi/lo bf16.
// ---------------------------------------------------------------------------
__global__ void __launch_bounds__(128) attn_kernel(
    const float* __restrict__ qkv,
    __nv_bfloat16* __restrict__ ohi, __nv_bfloat16* __restrict__ olo)
{
    const int s = blockIdx.x;
    const int h = blockIdx.y;

    __shared__ float q[BDIM][66];
    __shared__ float k[BDIM][66];
    __shared__ float v[BDIM][66];
    __shared__ float sc[BDIM][BDIM + 1];

    const int tid = threadIdx.x;

    for (int j = tid; j < BDIM * DH; j += 128) {
        const int b = j >> 6;
        const int d = j & 63;
        const size_t base = ((size_t)(b * SDIM + s)) * (3 * EDIM) + h * DH + d;
        q[b][d] = qkv[base];
        k[b][d] = qkv[base + EDIM];
        v[b][d] = qkv[base + 2 * EDIM];
    }
    __syncthreads();

    const float scale = 0.125f;
#pragma unroll
    for (int e = tid; e < BDIM * BDIM; e += 128) {
        const int bq = e >> 4;
        const int bk = e & 15;
        float acc = 0.0f;
#pragma unroll
        for (int d = 0; d < DH; d++)
            acc = fmaf(q[bq][d], k[bk][d], acc);
        sc[bq][bk] = acc * scale;
    }
    __syncthreads();

    if (tid < BDIM) {
        float m = -1e30f;
#pragma unroll
        for (int j = 0; j < BDIM; j++) m = fmaxf(m, sc[tid][j]);
        float sum = 0.0f;
        float e_[BDIM];
#pragma unroll
        for (int j = 0; j < BDIM; j++) { e_[j] = expf(sc[tid][j] - m); sum += e_[j]; }
        const float inv = 1.0f / sum;
#pragma unroll
        for (int j = 0; j < BDIM; j++) sc[tid][j] = e_[j] * inv;
    }
    __syncthreads();

    const int bq = tid >> 3;
    const int dl = tid & 7;
    const size_t obase = ((size_t)(bq * SDIM + s)) * EDIM + h * DH;
#pragma unroll
    for (int i = 0; i < 8; i++) {
        const int d = dl + i * 8;
        float acc = 0.0f;
#pragma unroll
        for (int bk = 0; bk < BDIM; bk++)
            acc = fmaf(sc[bq][bk], v[bk][d], acc);
        __nv_bfloat16 hi = __float2bfloat16(acc);
        ohi[obase + d] = hi;
        olo[obase + d] = __float2bfloat16(acc - __bfloat162float(hi));
    }
}

// ---------------------------------------------------------------------------
extern "C" void kernel_launch(void* const* d_in, const int* in_sizes, int n_in,
                              void* d_out, int out_size)
{
    const float* x     = (const float*)d_in[0];
    const float* W_in  = (const float*)d_in[1];
    const float* b_in  = (const float*)d_in[2];
    const float* W_out = (const float*)d_in[3];
    const float* b_out = (const float*)d_in[4];
    float* out = (float*)d_out;

    float *qkv;
    __nv_bfloat16 *xhi, *xlo, *ohi, *olo, *winhi, *winlo, *wouthi, *woutlo;
    cudaGetSymbolAddress((void**)&qkv, g_qkv);
    cudaGetSymbolAddress((void**)&xhi, g_xhi);
    cudaGetSymbolAddress((void**)&xlo, g_xlo);
    cudaGetSymbolAddress((void**)&ohi, g_ohi);
    cudaGetSymbolAddress((void**)&olo, g_olo);
    cudaGetSymbolAddress((void**)&winhi, g_winhi);
    cudaGetSymbolAddress((void**)&winlo, g_winlo);
    cudaGetSymbolAddress((void**)&wouthi, g_wouthi);
    cudaGetSymbolAddress((void**)&woutlo, g_woutlo);

    cudaFuncSetAttribute(gemm_hmma, cudaFuncAttributeMaxDynamicSharedMemorySize, GEMM_SMEM);

    // fp32 -> bf16 hi/lo splits
    {
        int n4 = TOK * EDIM / 4;
        split_hilo<<<(n4 + 255) / 256, 256>>>((const float4*)x, (uint2*)xhi, (uint2*)xlo, n4);
        n4 = 3 * EDIM * EDIM / 4;
        split_hilo<<<(n4 + 255) / 256, 256>>>((const float4*)W_in, (uint2*)winhi, (uint2*)winlo, n4);
        n4 = EDIM * EDIM / 4;
        split_hilo<<<(n4 + 255) / 256, 256>>>((const float4*)W_out, (uint2*)wouthi, (uint2*)woutlo, n4);
    }

    // 1) QKV projection -> fp32 qkv
    dim3 g1(3 * EDIM / 128, TOK / 128);
    gemm_hmma<<<g1, 256, GEMM_SMEM>>>(xhi, xlo, winhi, winlo, b_in, qkv, 3 * EDIM);

    // 2) Batch-axis attention; emits o split hi/lo bf16
    dim3 g2(SDIM, HDIM);
    attn_kernel<<<g2, 128>>>(qkv, ohi, olo);

    // 3) Output projection
    dim3 g3(EDIM / 128, TOK / 128);
    gemm_hmma<<<g3, 256, GEMM_SMEM>>>(ohi, olo, wouthi, woutlo, b_out, out, EDIM);
}